// round 1
// baseline (speedup 1.0000x reference)
#include <cuda_runtime.h>
#include <math.h>

#define BATCH 2
#define SEQL  2048
#define DMODEL 1024
#define NHEADS 16
#define DK    64
#define DFF   4096
#define TOKENS (BATCH*SEQL)   // 4096

// ---------------- scratch (device globals: allocation-guard safe) -----------
__device__ float g_q[TOKENS*DMODEL];
__device__ float g_k[TOKENS*DMODEL];
__device__ float g_v[TOKENS*DMODEL];
__device__ float g_attnv[TOKENS*DMODEL];
__device__ float g_tmp[TOKENS*DMODEL];
__device__ float g_x1[TOKENS*DMODEL];
__device__ float g_ff[TOKENS*DFF];
__device__ float g_tmp2[TOKENS*DMODEL];

// ---------------- SGEMM: C = A(MxK) @ B(KxN) + bias, optional exact GELU ----
// 128x128 tile, BK=8, 256 threads, 8x8 micro-tile per thread.
__global__ __launch_bounds__(256) void sgemm_bias(
    const float* __restrict__ A, const float* __restrict__ Bw,
    const float* __restrict__ bias, float* __restrict__ C,
    int M, int N, int K, int gelu)
{
    __shared__ float As[8][128];
    __shared__ float Bs[8][128];

    const int tid = threadIdx.x;
    const int tx = tid & 15;        // 0..15  (col group)
    const int ty = tid >> 4;        // 0..15  (row group)
    const int rowBase = blockIdx.y * 128;
    const int colBase = blockIdx.x * 128;

    // A tile loader: 128 rows x 8 cols = 256 float4
    const int aRow = tid >> 1;             // 0..127
    const int aCol = (tid & 1) * 4;        // 0 or 4
    // B tile loader: 8 rows x 128 cols = 256 float4
    const int bRow = tid >> 5;             // 0..7
    const int bCol = (tid & 31) * 4;       // 0..124

    const float* Ap = A  + (size_t)(rowBase + aRow) * K + aCol;
    const float* Bp = Bw + (size_t)bRow * N + colBase + bCol;

    float acc[8][8];
    #pragma unroll
    for (int i = 0; i < 8; i++)
        #pragma unroll
        for (int j = 0; j < 8; j++) acc[i][j] = 0.f;

    for (int k0 = 0; k0 < K; k0 += 8) {
        float4 a4 = *(const float4*)(Ap + k0);
        As[aCol + 0][aRow] = a4.x;
        As[aCol + 1][aRow] = a4.y;
        As[aCol + 2][aRow] = a4.z;
        As[aCol + 3][aRow] = a4.w;
        float4 b4 = *(const float4*)(Bp + (size_t)k0 * N);
        *(float4*)&Bs[bRow][bCol] = b4;
        __syncthreads();

        #pragma unroll
        for (int kk = 0; kk < 8; kk++) {
            float ar[8], br[8];
            *(float4*)&ar[0] = *(const float4*)&As[kk][ty * 8];
            *(float4*)&ar[4] = *(const float4*)&As[kk][ty * 8 + 4];
            *(float4*)&br[0] = *(const float4*)&Bs[kk][tx * 8];
            *(float4*)&br[4] = *(const float4*)&Bs[kk][tx * 8 + 4];
            #pragma unroll
            for (int i = 0; i < 8; i++)
                #pragma unroll
                for (int j = 0; j < 8; j++)
                    acc[i][j] = fmaf(ar[i], br[j], acc[i][j]);
        }
        __syncthreads();
    }

    #pragma unroll
    for (int i = 0; i < 8; i++) {
        const int r = rowBase + ty * 8 + i;
        float* crow = C + (size_t)r * N + colBase + tx * 8;
        #pragma unroll
        for (int j = 0; j < 8; j++) {
            float vv = acc[i][j] + bias[colBase + tx * 8 + j];
            if (gelu) vv = 0.5f * vv * (1.f + erff(vv * 0.70710678118654752f));
            crow[j] = vv;
        }
    }
}

// ---------------- flash attention (fp32, online softmax) -------------------
// Grid: (SEQL/128, BATCH*NHEADS). Block: 128 threads; 1 thread = 1 query row.
// Writes with the reference's no-transpose reshape scramble:
//   (b,h,l,kk) -> row h*128 + l/16, col (l%16)*64 + kk
__global__ __launch_bounds__(128, 1) void attn_kernel(
    const float* __restrict__ q, const float* __restrict__ k,
    const float* __restrict__ v, float* __restrict__ o_out)
{
    __shared__ float Ks[64][64];
    __shared__ float Vs[64][64];

    const int tid = threadIdx.x;
    const int bh = blockIdx.y;
    const int b  = bh >> 4;
    const int hh = bh & 15;
    const int l  = blockIdx.x * 128 + tid;

    const float* qrow = q + ((size_t)(b * SEQL + l)) * DMODEL + hh * DK;
    float qr[DK], o[DK];
    #pragma unroll
    for (int d = 0; d < DK; d++) { qr[d] = qrow[d]; o[d] = 0.f; }

    float m = -1e30f, lsum = 0.f;

    for (int kt = 0; kt < SEQL; kt += 64) {
        const float* kb = k + ((size_t)(b * SEQL + kt)) * DMODEL + hh * DK;
        const float* vb = v + ((size_t)(b * SEQL + kt)) * DMODEL + hh * DK;
        #pragma unroll
        for (int i = 0; i < 8; i++) {
            int f   = tid + i * 128;       // 0..1023 float4 slots
            int key = f >> 4;
            int d4  = (f & 15) * 4;
            *(float4*)&Ks[key][d4] = *(const float4*)(kb + (size_t)key * DMODEL + d4);
            *(float4*)&Vs[key][d4] = *(const float4*)(vb + (size_t)key * DMODEL + d4);
        }
        __syncthreads();

        for (int jc = 0; jc < 64; jc += 16) {
            float s[16];
            #pragma unroll
            for (int j = 0; j < 16; j++) {
                float a = 0.f;
                #pragma unroll
                for (int d = 0; d < DK; d++) a = fmaf(qr[d], Ks[jc + j][d], a);
                s[j] = a * 0.125f;   // 1/sqrt(64)
            }
            float mn = m;
            #pragma unroll
            for (int j = 0; j < 16; j++) mn = fmaxf(mn, s[j]);
            float scale = __expf(m - mn);
            m = mn;
            lsum *= scale;
            #pragma unroll
            for (int d = 0; d < DK; d++) o[d] *= scale;
            #pragma unroll
            for (int j = 0; j < 16; j++) {
                float p = __expf(s[j] - m);
                lsum += p;
                #pragma unroll
                for (int d = 0; d < DK; d++) o[d] = fmaf(p, Vs[jc + j][d], o[d]);
            }
        }
        __syncthreads();
    }

    const float inv = 1.f / lsum;
    const int lr = hh * 128 + (l >> 4);
    const int dc = (l & 15) * 64;
    float* dst = o_out + ((size_t)(b * SEQL + lr)) * DMODEL + dc;
    #pragma unroll
    for (int d = 0; d < DK; d += 4) {
        float4 w = make_float4(o[d] * inv, o[d + 1] * inv, o[d + 2] * inv, o[d + 3] * inv);
        *(float4*)(dst + d) = w;
    }
}

// ---------------- residual add + LayerNorm ----------------------------------
// Grid: TOKENS blocks, 256 threads; d = 1024 -> 4 elems/thread.
__global__ __launch_bounds__(256) void add_ln_kernel(
    const float* __restrict__ a, const float* __restrict__ b,
    const float* __restrict__ g, const float* __restrict__ beta,
    float* __restrict__ out)
{
    const int row = blockIdx.x;
    const int tid = threadIdx.x;
    const float* ar = a + (size_t)row * DMODEL;
    const float* br = b + (size_t)row * DMODEL;

    float x[4];
    float sum = 0.f, sq = 0.f;
    #pragma unroll
    for (int i = 0; i < 4; i++) {
        int c = tid + i * 256;
        x[i] = ar[c] + br[c];
        sum += x[i];
        sq  += x[i] * x[i];
    }
    #pragma unroll
    for (int off = 16; off; off >>= 1) {
        sum += __shfl_xor_sync(0xffffffffu, sum, off);
        sq  += __shfl_xor_sync(0xffffffffu, sq, off);
    }
    __shared__ float ssum[8], ssq[8];
    const int wid = tid >> 5;
    if ((tid & 31) == 0) { ssum[wid] = sum; ssq[wid] = sq; }
    __syncthreads();
    sum = 0.f; sq = 0.f;
    #pragma unroll
    for (int w = 0; w < 8; w++) { sum += ssum[w]; sq += ssq[w]; }

    const float mean = sum * (1.f / DMODEL);
    const float var  = sq * (1.f / DMODEL) - mean * mean;
    const float rstd = rsqrtf(var + 1e-5f);

    float* orow = out + (size_t)row * DMODEL;
    #pragma unroll
    for (int i = 0; i < 4; i++) {
        int c = tid + i * 256;
        orow[c] = (x[i] - mean) * rstd * g[c] + beta[c];
    }
}

// ---------------- launch ----------------------------------------------------
extern "C" void kernel_launch(void* const* d_in, const int* in_sizes, int n_in,
                              void* d_out, int out_size)
{
    const float* x    = (const float*)d_in[0];
    const float* Wq   = (const float*)d_in[1];
    const float* bq   = (const float*)d_in[2];
    const float* Wk   = (const float*)d_in[3];
    const float* bk   = (const float*)d_in[4];
    const float* Wv   = (const float*)d_in[5];
    const float* bv   = (const float*)d_in[6];
    const float* Wo   = (const float*)d_in[7];
    const float* bo   = (const float*)d_in[8];
    const float* W1   = (const float*)d_in[9];
    const float* b1   = (const float*)d_in[10];
    const float* W2   = (const float*)d_in[11];
    const float* b2   = (const float*)d_in[12];
    const float* g1   = (const float*)d_in[13];
    const float* bt1  = (const float*)d_in[14];
    const float* g2   = (const float*)d_in[15];
    const float* bt2  = (const float*)d_in[16];
    float* out = (float*)d_out;

    float *q, *k, *v, *attnv, *tmp, *x1, *ff, *tmp2;
    cudaGetSymbolAddress((void**)&q,     g_q);
    cudaGetSymbolAddress((void**)&k,     g_k);
    cudaGetSymbolAddress((void**)&v,     g_v);
    cudaGetSymbolAddress((void**)&attnv, g_attnv);
    cudaGetSymbolAddress((void**)&tmp,   g_tmp);
    cudaGetSymbolAddress((void**)&x1,    g_x1);
    cudaGetSymbolAddress((void**)&ff,    g_ff);
    cudaGetSymbolAddress((void**)&tmp2,  g_tmp2);

    dim3 gD(DMODEL / 128, TOKENS / 128);   // (8, 32)
    dim3 gF(DFF / 128, TOKENS / 128);      // (32, 32)

    // QKV projections
    sgemm_bias<<<gD, 256>>>(x, Wq, bq, q, TOKENS, DMODEL, DMODEL, 0);
    sgemm_bias<<<gD, 256>>>(x, Wk, bk, k, TOKENS, DMODEL, DMODEL, 0);
    sgemm_bias<<<gD, 256>>>(x, Wv, bv, v, TOKENS, DMODEL, DMODEL, 0);

    // attention (with reference's no-transpose reshape in the epilogue)
    dim3 gA(SEQL / 128, BATCH * NHEADS);   // (16, 32)
    attn_kernel<<<gA, 128>>>(q, k, v, attnv);

    // output projection + residual LN
    sgemm_bias<<<gD, 256>>>(attnv, Wo, bo, tmp, TOKENS, DMODEL, DMODEL, 0);
    add_ln_kernel<<<TOKENS, 256>>>(tmp, x, g1, bt1, x1);

    // FFN
    sgemm_bias<<<gF, 256>>>(x1, W1, b1, ff, TOKENS, DFF, DMODEL, 1);
    sgemm_bias<<<gD, 256>>>(ff, W2, b2, tmp2, TOKENS, DMODEL, DFF, 0);
    add_ln_kernel<<<TOKENS, 256>>>(tmp2, x1, g2, bt2, out);
}

// round 2
// speedup vs baseline: 1.9594x; 1.9594x over previous
#include <cuda_runtime.h>
#include <math.h>
#include <stdint.h>

#define BATCH 2
#define SEQL  2048
#define DMODEL 1024
#define NHEADS 16
#define DK    64
#define DFF   4096
#define TOKENS (BATCH*SEQL)   // 4096

// ---------------- scratch (device globals: allocation-guard safe) -----------
__device__ float g_q[TOKENS*DMODEL];
__device__ float g_k[TOKENS*DMODEL];
__device__ float g_v[TOKENS*DMODEL];
__device__ float g_attnv[TOKENS*DMODEL];
__device__ float g_tmp[TOKENS*DMODEL];
__device__ float g_x1[TOKENS*DMODEL];
__device__ float g_ff[TOKENS*DFF];
__device__ float g_tmp2[TOKENS*DMODEL];

// ---------------- tf32 helpers ----------------------------------------------
__device__ __forceinline__ uint32_t f2tf32(float x) {
    uint32_t r;
    asm("cvt.rna.tf32.f32 %0, %1;" : "=r"(r) : "f"(x));
    return r;
}

__device__ __forceinline__ void mma_tf32(float c[4],
    uint32_t a0, uint32_t a1, uint32_t a2, uint32_t a3,
    uint32_t b0, uint32_t b1)
{
    asm volatile(
        "mma.sync.aligned.m16n8k8.row.col.f32.tf32.tf32.f32 "
        "{%0,%1,%2,%3}, {%4,%5,%6,%7}, {%8,%9}, {%0,%1,%2,%3};"
        : "+f"(c[0]), "+f"(c[1]), "+f"(c[2]), "+f"(c[3])
        : "r"(a0), "r"(a1), "r"(a2), "r"(a3), "r"(b0), "r"(b1));
}

// ---------------- TF32 tensor-core GEMM: C = A(MxK)@B(KxN) + bias [+GELU] ---
// 128x128 tile, BK=32, 256 threads (8 warps, warp tile 64x32), m16n8k8 tf32.
// Register-prefetch double buffering; tf32 cvt at STS time.
__global__ __launch_bounds__(256) void tgemm_bias(
    const float* __restrict__ A, const float* __restrict__ Bw,
    const float* __restrict__ bias, float* __restrict__ C,
    int M, int N, int K, int gelu)
{
    // pads chosen for conflict-free fragment LDS:
    //  As[r][c] banks = (36r + c) mod 32 = (4*(lane>>2) + (lane&3)) = lane
    //  Bs[r][c] banks = (136r + c) mod 32 = (8*(lane&3) + (lane>>2)) distinct
    __shared__ uint32_t As[128][36];
    __shared__ uint32_t Bs[32][136];

    const int tid  = threadIdx.x;
    const int lane = tid & 31;
    const int warp = tid >> 5;
    const int wm   = (warp & 1) * 64;   // warp row base within tile
    const int wn   = (warp >> 1) * 32;  // warp col base within tile
    const int rowBase = blockIdx.y * 128;
    const int colBase = blockIdx.x * 128;

    // loaders: A tile 128x32 (8 float4/row), B tile 32x128 (32 float4/row)
    // each thread: 4 float4 from A, 4 from B
    float4 aregs[4], bregs[4];

    float acc[4][4][4];
    #pragma unroll
    for (int i = 0; i < 4; i++)
        #pragma unroll
        for (int j = 0; j < 4; j++)
            #pragma unroll
            for (int r = 0; r < 4; r++) acc[i][j][r] = 0.f;

    // prologue: fetch k0 = 0
    #pragma unroll
    for (int i = 0; i < 4; i++) {
        int f = tid + i * 256;
        int ar = f >> 3, ac = (f & 7) * 4;
        int br = f >> 5, bc = (f & 31) * 4;
        aregs[i] = *(const float4*)(A  + (size_t)(rowBase + ar) * K + ac);
        bregs[i] = *(const float4*)(Bw + (size_t)br * N + colBase + bc);
    }

    for (int k0 = 0; k0 < K; k0 += 32) {
        __syncthreads();   // previous compute done before overwriting smem
        #pragma unroll
        for (int i = 0; i < 4; i++) {
            int f = tid + i * 256;
            int ar = f >> 3, ac = (f & 7) * 4;
            int br = f >> 5, bc = (f & 31) * 4;
            As[ar][ac + 0] = f2tf32(aregs[i].x);
            As[ar][ac + 1] = f2tf32(aregs[i].y);
            As[ar][ac + 2] = f2tf32(aregs[i].z);
            As[ar][ac + 3] = f2tf32(aregs[i].w);
            Bs[br][bc + 0] = f2tf32(bregs[i].x);
            Bs[br][bc + 1] = f2tf32(bregs[i].y);
            Bs[br][bc + 2] = f2tf32(bregs[i].z);
            Bs[br][bc + 3] = f2tf32(bregs[i].w);
        }
        __syncthreads();

        if (k0 + 32 < K) {
            #pragma unroll
            for (int i = 0; i < 4; i++) {
                int f = tid + i * 256;
                int ar = f >> 3, ac = (f & 7) * 4;
                int br = f >> 5, bc = (f & 31) * 4;
                aregs[i] = *(const float4*)(A  + (size_t)(rowBase + ar) * K + k0 + 32 + ac);
                bregs[i] = *(const float4*)(Bw + (size_t)(k0 + 32 + br) * N + colBase + bc);
            }
        }

        #pragma unroll
        for (int kk = 0; kk < 4; kk++) {
            uint32_t af[4][4], bf[4][2];
            #pragma unroll
            for (int mf = 0; mf < 4; mf++) {
                int r = wm + mf * 16 + (lane >> 2);
                int c = kk * 8 + (lane & 3);
                af[mf][0] = As[r][c];
                af[mf][1] = As[r + 8][c];
                af[mf][2] = As[r][c + 4];
                af[mf][3] = As[r + 8][c + 4];
            }
            #pragma unroll
            for (int nf = 0; nf < 4; nf++) {
                int c = wn + nf * 8 + (lane >> 2);
                int r = kk * 8 + (lane & 3);
                bf[nf][0] = Bs[r][c];
                bf[nf][1] = Bs[r + 4][c];
            }
            #pragma unroll
            for (int mf = 0; mf < 4; mf++)
                #pragma unroll
                for (int nf = 0; nf < 4; nf++)
                    mma_tf32(acc[mf][nf], af[mf][0], af[mf][1], af[mf][2], af[mf][3],
                             bf[nf][0], bf[nf][1]);
        }
    }

    // epilogue: c0,c1 -> (row, col), (row, col+1); c2,c3 -> row+8
    #pragma unroll
    for (int mf = 0; mf < 4; mf++) {
        #pragma unroll
        for (int nf = 0; nf < 4; nf++) {
            int row = rowBase + wm + mf * 16 + (lane >> 2);
            int col = colBase + wn + nf * 8 + 2 * (lane & 3);
            float v0 = acc[mf][nf][0] + bias[col];
            float v1 = acc[mf][nf][1] + bias[col + 1];
            float v2 = acc[mf][nf][2] + bias[col];
            float v3 = acc[mf][nf][3] + bias[col + 1];
            if (gelu) {
                v0 = 0.5f * v0 * (1.f + erff(v0 * 0.70710678118654752f));
                v1 = 0.5f * v1 * (1.f + erff(v1 * 0.70710678118654752f));
                v2 = 0.5f * v2 * (1.f + erff(v2 * 0.70710678118654752f));
                v3 = 0.5f * v3 * (1.f + erff(v3 * 0.70710678118654752f));
            }
            *(float2*)(C + (size_t)row * N + col)       = make_float2(v0, v1);
            *(float2*)(C + (size_t)(row + 8) * N + col) = make_float2(v2, v3);
        }
    }
}

// ---------------- flash attention (fp32, online softmax) -------------------
__global__ __launch_bounds__(128, 1) void attn_kernel(
    const float* __restrict__ q, const float* __restrict__ k,
    const float* __restrict__ v, float* __restrict__ o_out)
{
    __shared__ float Ks[64][64];
    __shared__ float Vs[64][64];

    const int tid = threadIdx.x;
    const int bh = blockIdx.y;
    const int b  = bh >> 4;
    const int hh = bh & 15;
    const int l  = blockIdx.x * 128 + tid;

    const float* qrow = q + ((size_t)(b * SEQL + l)) * DMODEL + hh * DK;
    float qr[DK], o[DK];
    #pragma unroll
    for (int d = 0; d < DK; d++) { qr[d] = qrow[d]; o[d] = 0.f; }

    float m = -1e30f, lsum = 0.f;

    for (int kt = 0; kt < SEQL; kt += 64) {
        const float* kb = k + ((size_t)(b * SEQL + kt)) * DMODEL + hh * DK;
        const float* vb = v + ((size_t)(b * SEQL + kt)) * DMODEL + hh * DK;
        #pragma unroll
        for (int i = 0; i < 8; i++) {
            int f   = tid + i * 128;
            int key = f >> 4;
            int d4  = (f & 15) * 4;
            *(float4*)&Ks[key][d4] = *(const float4*)(kb + (size_t)key * DMODEL + d4);
            *(float4*)&Vs[key][d4] = *(const float4*)(vb + (size_t)key * DMODEL + d4);
        }
        __syncthreads();

        for (int jc = 0; jc < 64; jc += 16) {
            float s[16];
            #pragma unroll
            for (int j = 0; j < 16; j++) {
                float a = 0.f;
                #pragma unroll
                for (int d = 0; d < DK; d++) a = fmaf(qr[d], Ks[jc + j][d], a);
                s[j] = a * 0.125f;
            }
            float mn = m;
            #pragma unroll
            for (int j = 0; j < 16; j++) mn = fmaxf(mn, s[j]);
            float scale = __expf(m - mn);
            m = mn;
            lsum *= scale;
            #pragma unroll
            for (int d = 0; d < DK; d++) o[d] *= scale;
            #pragma unroll
            for (int j = 0; j < 16; j++) {
                float p = __expf(s[j] - m);
                lsum += p;
                #pragma unroll
                for (int d = 0; d < DK; d++) o[d] = fmaf(p, Vs[jc + j][d], o[d]);
            }
        }
        __syncthreads();
    }

    const float inv = 1.f / lsum;
    const int lr = hh * 128 + (l >> 4);
    const int dc = (l & 15) * 64;
    float* dst = o_out + ((size_t)(b * SEQL + lr)) * DMODEL + dc;
    #pragma unroll
    for (int d = 0; d < DK; d += 4) {
        float4 w = make_float4(o[d] * inv, o[d + 1] * inv, o[d + 2] * inv, o[d + 3] * inv);
        *(float4*)(dst + d) = w;
    }
}

// ---------------- residual add + LayerNorm ----------------------------------
__global__ __launch_bounds__(256) void add_ln_kernel(
    const float* __restrict__ a, const float* __restrict__ b,
    const float* __restrict__ g, const float* __restrict__ beta,
    float* __restrict__ out)
{
    const int row = blockIdx.x;
    const int tid = threadIdx.x;
    const float* ar = a + (size_t)row * DMODEL;
    const float* br = b + (size_t)row * DMODEL;

    float x[4];
    float sum = 0.f, sq = 0.f;
    #pragma unroll
    for (int i = 0; i < 4; i++) {
        int c = tid + i * 256;
        x[i] = ar[c] + br[c];
        sum += x[i];
        sq  += x[i] * x[i];
    }
    #pragma unroll
    for (int off = 16; off; off >>= 1) {
        sum += __shfl_xor_sync(0xffffffffu, sum, off);
        sq  += __shfl_xor_sync(0xffffffffu, sq, off);
    }
    __shared__ float ssum[8], ssq[8];
    const int wid = tid >> 5;
    if ((tid & 31) == 0) { ssum[wid] = sum; ssq[wid] = sq; }
    __syncthreads();
    sum = 0.f; sq = 0.f;
    #pragma unroll
    for (int w = 0; w < 8; w++) { sum += ssum[w]; sq += ssq[w]; }

    const float mean = sum * (1.f / DMODEL);
    const float var  = sq * (1.f / DMODEL) - mean * mean;
    const float rstd = rsqrtf(var + 1e-5f);

    float* orow = out + (size_t)row * DMODEL;
    #pragma unroll
    for (int i = 0; i < 4; i++) {
        int c = tid + i * 256;
        orow[c] = (x[i] - mean) * rstd * g[c] + beta[c];
    }
}

// ---------------- launch ----------------------------------------------------
extern "C" void kernel_launch(void* const* d_in, const int* in_sizes, int n_in,
                              void* d_out, int out_size)
{
    const float* x    = (const float*)d_in[0];
    const float* Wq   = (const float*)d_in[1];
    const float* bq   = (const float*)d_in[2];
    const float* Wk   = (const float*)d_in[3];
    const float* bk   = (const float*)d_in[4];
    const float* Wv   = (const float*)d_in[5];
    const float* bv   = (const float*)d_in[6];
    const float* Wo   = (const float*)d_in[7];
    const float* bo   = (const float*)d_in[8];
    const float* W1   = (const float*)d_in[9];
    const float* b1   = (const float*)d_in[10];
    const float* W2   = (const float*)d_in[11];
    const float* b2   = (const float*)d_in[12];
    const float* g1   = (const float*)d_in[13];
    const float* bt1  = (const float*)d_in[14];
    const float* g2   = (const float*)d_in[15];
    const float* bt2  = (const float*)d_in[16];
    float* out = (float*)d_out;

    float *q, *k, *v, *attnv, *tmp, *x1, *ff, *tmp2;
    cudaGetSymbolAddress((void**)&q,     g_q);
    cudaGetSymbolAddress((void**)&k,     g_k);
    cudaGetSymbolAddress((void**)&v,     g_v);
    cudaGetSymbolAddress((void**)&attnv, g_attnv);
    cudaGetSymbolAddress((void**)&tmp,   g_tmp);
    cudaGetSymbolAddress((void**)&x1,    g_x1);
    cudaGetSymbolAddress((void**)&ff,    g_ff);
    cudaGetSymbolAddress((void**)&tmp2,  g_tmp2);

    dim3 gD(DMODEL / 128, TOKENS / 128);   // (8, 32)
    dim3 gF(DFF / 128, TOKENS / 128);      // (32, 32)

    // QKV projections (tf32 tensor cores)
    tgemm_bias<<<gD, 256>>>(x, Wq, bq, q, TOKENS, DMODEL, DMODEL, 0);
    tgemm_bias<<<gD, 256>>>(x, Wk, bk, k, TOKENS, DMODEL, DMODEL, 0);
    tgemm_bias<<<gD, 256>>>(x, Wv, bv, v, TOKENS, DMODEL, DMODEL, 0);

    // attention (with reference's no-transpose reshape in the epilogue)
    dim3 gA(SEQL / 128, BATCH * NHEADS);   // (16, 32)
    attn_kernel<<<gA, 128>>>(q, k, v, attnv);

    // output projection + residual LN
    tgemm_bias<<<gD, 256>>>(attnv, Wo, bo, tmp, TOKENS, DMODEL, DMODEL, 0);
    add_ln_kernel<<<TOKENS, 256>>>(tmp, x, g1, bt1, x1);

    // FFN
    tgemm_bias<<<gF, 256>>>(x1, W1, b1, ff, TOKENS, DFF, DMODEL, 1);
    tgemm_bias<<<gD, 256>>>(ff, W2, b2, tmp2, TOKENS, DMODEL, DFF, 0);
    add_ln_kernel<<<TOKENS, 256>>>(tmp2, x1, g2, bt2, out);
}

// round 3
// speedup vs baseline: 3.5173x; 1.7951x over previous
#include <cuda_runtime.h>
#include <math.h>
#include <stdint.h>

#define BATCH 2
#define SEQL  2048
#define DMODEL 1024
#define NHEADS 16
#define DK    64
#define DFF   4096
#define TOKENS (BATCH*SEQL)   // 4096

// ---------------- scratch (device globals: allocation-guard safe) -----------
__device__ float g_q[TOKENS*DMODEL];
__device__ float g_k[TOKENS*DMODEL];
__device__ float g_v[TOKENS*DMODEL];
__device__ float g_attnv[TOKENS*DMODEL];
__device__ float g_tmp[TOKENS*DMODEL];
__device__ float g_x1[TOKENS*DMODEL];
__device__ float g_ff[TOKENS*DFF];
__device__ float g_tmp2[TOKENS*DMODEL];

// ---------------- tf32 helpers ----------------------------------------------
__device__ __forceinline__ uint32_t f2tf32(float x) {
    uint32_t r;
    asm("cvt.rna.tf32.f32 %0, %1;" : "=r"(r) : "f"(x));
    return r;
}

__device__ __forceinline__ void mma_tf32(float c[4],
    uint32_t a0, uint32_t a1, uint32_t a2, uint32_t a3,
    uint32_t b0, uint32_t b1)
{
    asm volatile(
        "mma.sync.aligned.m16n8k8.row.col.f32.tf32.tf32.f32 "
        "{%0,%1,%2,%3}, {%4,%5,%6,%7}, {%8,%9}, {%0,%1,%2,%3};"
        : "+f"(c[0]), "+f"(c[1]), "+f"(c[2]), "+f"(c[3])
        : "r"(a0), "r"(a1), "r"(a2), "r"(a3), "r"(b0), "r"(b1));
}

// ---------------- TF32 tensor-core GEMM: C = A(MxK)@B(KxN) + bias [+GELU] ---
__global__ __launch_bounds__(256) void tgemm_bias(
    const float* __restrict__ A, const float* __restrict__ Bw,
    const float* __restrict__ bias, float* __restrict__ C,
    int M, int N, int K, int gelu)
{
    __shared__ uint32_t As[128][36];
    __shared__ uint32_t Bs[32][136];

    const int tid  = threadIdx.x;
    const int lane = tid & 31;
    const int warp = tid >> 5;
    const int wm   = (warp & 1) * 64;
    const int wn   = (warp >> 1) * 32;
    const int rowBase = blockIdx.y * 128;
    const int colBase = blockIdx.x * 128;

    float4 aregs[4], bregs[4];

    float acc[4][4][4];
    #pragma unroll
    for (int i = 0; i < 4; i++)
        #pragma unroll
        for (int j = 0; j < 4; j++)
            #pragma unroll
            for (int r = 0; r < 4; r++) acc[i][j][r] = 0.f;

    #pragma unroll
    for (int i = 0; i < 4; i++) {
        int f = tid + i * 256;
        int ar = f >> 3, ac = (f & 7) * 4;
        int br = f >> 5, bc = (f & 31) * 4;
        aregs[i] = *(const float4*)(A  + (size_t)(rowBase + ar) * K + ac);
        bregs[i] = *(const float4*)(Bw + (size_t)br * N + colBase + bc);
    }

    for (int k0 = 0; k0 < K; k0 += 32) {
        __syncthreads();
        #pragma unroll
        for (int i = 0; i < 4; i++) {
            int f = tid + i * 256;
            int ar = f >> 3, ac = (f & 7) * 4;
            int br = f >> 5, bc = (f & 31) * 4;
            As[ar][ac + 0] = f2tf32(aregs[i].x);
            As[ar][ac + 1] = f2tf32(aregs[i].y);
            As[ar][ac + 2] = f2tf32(aregs[i].z);
            As[ar][ac + 3] = f2tf32(aregs[i].w);
            Bs[br][bc + 0] = f2tf32(bregs[i].x);
            Bs[br][bc + 1] = f2tf32(bregs[i].y);
            Bs[br][bc + 2] = f2tf32(bregs[i].z);
            Bs[br][bc + 3] = f2tf32(bregs[i].w);
        }
        __syncthreads();

        if (k0 + 32 < K) {
            #pragma unroll
            for (int i = 0; i < 4; i++) {
                int f = tid + i * 256;
                int ar = f >> 3, ac = (f & 7) * 4;
                int br = f >> 5, bc = (f & 31) * 4;
                aregs[i] = *(const float4*)(A  + (size_t)(rowBase + ar) * K + k0 + 32 + ac);
                bregs[i] = *(const float4*)(Bw + (size_t)(k0 + 32 + br) * N + colBase + bc);
            }
        }

        #pragma unroll
        for (int kk = 0; kk < 4; kk++) {
            uint32_t af[4][4], bf[4][2];
            #pragma unroll
            for (int mf = 0; mf < 4; mf++) {
                int r = wm + mf * 16 + (lane >> 2);
                int c = kk * 8 + (lane & 3);
                af[mf][0] = As[r][c];
                af[mf][1] = As[r + 8][c];
                af[mf][2] = As[r][c + 4];
                af[mf][3] = As[r + 8][c + 4];
            }
            #pragma unroll
            for (int nf = 0; nf < 4; nf++) {
                int c = wn + nf * 8 + (lane >> 2);
                int r = kk * 8 + (lane & 3);
                bf[nf][0] = Bs[r][c];
                bf[nf][1] = Bs[r + 4][c];
            }
            #pragma unroll
            for (int mf = 0; mf < 4; mf++)
                #pragma unroll
                for (int nf = 0; nf < 4; nf++)
                    mma_tf32(acc[mf][nf], af[mf][0], af[mf][1], af[mf][2], af[mf][3],
                             bf[nf][0], bf[nf][1]);
        }
    }

    #pragma unroll
    for (int mf = 0; mf < 4; mf++) {
        #pragma unroll
        for (int nf = 0; nf < 4; nf++) {
            int row = rowBase + wm + mf * 16 + (lane >> 2);
            int col = colBase + wn + nf * 8 + 2 * (lane & 3);
            float v0 = acc[mf][nf][0] + bias[col];
            float v1 = acc[mf][nf][1] + bias[col + 1];
            float v2 = acc[mf][nf][2] + bias[col];
            float v3 = acc[mf][nf][3] + bias[col + 1];
            if (gelu) {
                v0 = 0.5f * v0 * (1.f + erff(v0 * 0.70710678118654752f));
                v1 = 0.5f * v1 * (1.f + erff(v1 * 0.70710678118654752f));
                v2 = 0.5f * v2 * (1.f + erff(v2 * 0.70710678118654752f));
                v3 = 0.5f * v3 * (1.f + erff(v3 * 0.70710678118654752f));
            }
            *(float2*)(C + (size_t)row * N + col)       = make_float2(v0, v1);
            *(float2*)(C + (size_t)(row + 8) * N + col) = make_float2(v2, v3);
        }
    }
}

// ---------------- tensor-core flash attention (tf32 mma, online softmax) ----
// Block: 256 thr (8 warps), 128 query rows (16 per warp), key tiles of 128.
// Padded smem: Ks[128][68], Vs[128][72], Ps[128][132] -> conflict-free frag LDS.
#define KS_PAD 68
#define VS_PAD 72
#define PS_PAD 132
#define ATT_SMEM_WORDS (128*KS_PAD + 128*VS_PAD + 128*PS_PAD)
#define ATT_SMEM_BYTES (ATT_SMEM_WORDS * 4)

__global__ __launch_bounds__(256, 1) void attn_tc(
    const float* __restrict__ q, const float* __restrict__ k,
    const float* __restrict__ v, float* __restrict__ o_out)
{
    extern __shared__ uint32_t sm[];
    uint32_t* Ks = sm;                          // [128][KS_PAD]
    uint32_t* Vs = sm + 128 * KS_PAD;           // [128][VS_PAD]
    uint32_t* Ps = sm + 128 * (KS_PAD + VS_PAD);// [128][PS_PAD]

    const int tid  = threadIdx.x;
    const int lane = tid & 31;
    const int warp = tid >> 5;
    const int r4 = lane >> 2;     // 0..7
    const int q4 = lane & 3;      // 0..3
    const int bh = blockIdx.y;
    const int b  = bh >> 4;
    const int hh = bh & 15;
    const int qbase = blockIdx.x * 128;
    const int wrow  = warp * 16;  // warp's first local query row

    // Q fragments (16 rows x 64 d), scaled by 1/sqrt(dk), resident in regs
    uint32_t qf[8][4];
    {
        const float* qp = q + ((size_t)(b * SEQL + qbase + wrow)) * DMODEL + hh * DK;
        #pragma unroll
        for (int kk = 0; kk < 8; kk++) {
            qf[kk][0] = f2tf32(qp[(size_t)r4       * DMODEL + kk * 8 + q4    ] * 0.125f);
            qf[kk][1] = f2tf32(qp[(size_t)(r4 + 8) * DMODEL + kk * 8 + q4    ] * 0.125f);
            qf[kk][2] = f2tf32(qp[(size_t)r4       * DMODEL + kk * 8 + q4 + 4] * 0.125f);
            qf[kk][3] = f2tf32(qp[(size_t)(r4 + 8) * DMODEL + kk * 8 + q4 + 4] * 0.125f);
        }
    }

    float oacc[8][4];
    #pragma unroll
    for (int nf = 0; nf < 8; nf++)
        #pragma unroll
        for (int r = 0; r < 4; r++) oacc[nf][r] = 0.f;

    float m0 = -1e30f, m8 = -1e30f, l0 = 0.f, l8 = 0.f;

    for (int kt = 0; kt < SEQL; kt += 128) {
        __syncthreads();   // previous tile's smem reads complete
        // fill K/V tiles (tf32)
        {
            const float* kb = k + ((size_t)(b * SEQL + kt)) * DMODEL + hh * DK;
            const float* vb = v + ((size_t)(b * SEQL + kt)) * DMODEL + hh * DK;
            #pragma unroll
            for (int i = 0; i < 8; i++) {
                int f   = tid + i * 256;
                int key = f >> 4;
                int d4  = (f & 15) * 4;
                float4 kv = *(const float4*)(kb + (size_t)key * DMODEL + d4);
                float4 vv = *(const float4*)(vb + (size_t)key * DMODEL + d4);
                uint32_t* kd = Ks + key * KS_PAD + d4;
                kd[0] = f2tf32(kv.x); kd[1] = f2tf32(kv.y);
                kd[2] = f2tf32(kv.z); kd[3] = f2tf32(kv.w);
                uint32_t* vd = Vs + key * VS_PAD + d4;
                vd[0] = f2tf32(vv.x); vd[1] = f2tf32(vv.y);
                vd[2] = f2tf32(vv.z); vd[3] = f2tf32(vv.w);
            }
        }
        __syncthreads();

        // S = Q @ K^T  (16 x 128 per warp)
        float sacc[16][4];
        #pragma unroll
        for (int nf = 0; nf < 16; nf++)
            #pragma unroll
            for (int r = 0; r < 4; r++) sacc[nf][r] = 0.f;

        #pragma unroll
        for (int kk = 0; kk < 8; kk++) {
            #pragma unroll
            for (int nf = 0; nf < 16; nf++) {
                uint32_t b0 = Ks[(nf * 8 + r4) * KS_PAD + kk * 8 + q4];
                uint32_t b1 = Ks[(nf * 8 + r4) * KS_PAD + kk * 8 + q4 + 4];
                mma_tf32(sacc[nf], qf[kk][0], qf[kk][1], qf[kk][2], qf[kk][3], b0, b1);
            }
        }

        // online softmax (rows r4 and r4+8; full row lives in this quad)
        float mx0 = -1e30f, mx8 = -1e30f;
        #pragma unroll
        for (int nf = 0; nf < 16; nf++) {
            mx0 = fmaxf(mx0, fmaxf(sacc[nf][0], sacc[nf][1]));
            mx8 = fmaxf(mx8, fmaxf(sacc[nf][2], sacc[nf][3]));
        }
        mx0 = fmaxf(mx0, __shfl_xor_sync(0xffffffffu, mx0, 1));
        mx0 = fmaxf(mx0, __shfl_xor_sync(0xffffffffu, mx0, 2));
        mx8 = fmaxf(mx8, __shfl_xor_sync(0xffffffffu, mx8, 1));
        mx8 = fmaxf(mx8, __shfl_xor_sync(0xffffffffu, mx8, 2));

        float mn0 = fmaxf(m0, mx0);
        float mn8 = fmaxf(m8, mx8);
        float sc0 = __expf(m0 - mn0);
        float sc8 = __expf(m8 - mn8);
        m0 = mn0; m8 = mn8;
        l0 *= sc0; l8 *= sc8;
        #pragma unroll
        for (int nf = 0; nf < 8; nf++) {
            oacc[nf][0] *= sc0; oacc[nf][1] *= sc0;
            oacc[nf][2] *= sc8; oacc[nf][3] *= sc8;
        }

        float rs0 = 0.f, rs8 = 0.f;
        uint32_t* pw0 = Ps + (wrow + r4) * PS_PAD;
        uint32_t* pw8 = Ps + (wrow + r4 + 8) * PS_PAD;
        #pragma unroll
        for (int nf = 0; nf < 16; nf++) {
            float p0 = __expf(sacc[nf][0] - m0);
            float p1 = __expf(sacc[nf][1] - m0);
            float p2 = __expf(sacc[nf][2] - m8);
            float p3 = __expf(sacc[nf][3] - m8);
            rs0 += p0 + p1; rs8 += p2 + p3;
            int col = nf * 8 + 2 * q4;
            pw0[col] = f2tf32(p0); pw0[col + 1] = f2tf32(p1);
            pw8[col] = f2tf32(p2); pw8[col + 1] = f2tf32(p3);
        }
        rs0 += __shfl_xor_sync(0xffffffffu, rs0, 1);
        rs0 += __shfl_xor_sync(0xffffffffu, rs0, 2);
        rs8 += __shfl_xor_sync(0xffffffffu, rs8, 1);
        rs8 += __shfl_xor_sync(0xffffffffu, rs8, 2);
        l0 += rs0; l8 += rs8;
        __syncwarp();   // P rows are warp-private: warp-level sync suffices

        // O += P @ V  (16 x 64 per warp, k = 128 keys)
        #pragma unroll
        for (int kk = 0; kk < 16; kk++) {
            uint32_t a0 = Ps[(wrow + r4)     * PS_PAD + kk * 8 + q4];
            uint32_t a1 = Ps[(wrow + r4 + 8) * PS_PAD + kk * 8 + q4];
            uint32_t a2 = Ps[(wrow + r4)     * PS_PAD + kk * 8 + q4 + 4];
            uint32_t a3 = Ps[(wrow + r4 + 8) * PS_PAD + kk * 8 + q4 + 4];
            #pragma unroll
            for (int nf = 0; nf < 8; nf++) {
                uint32_t b0 = Vs[(kk * 8 + q4)     * VS_PAD + nf * 8 + r4];
                uint32_t b1 = Vs[(kk * 8 + q4 + 4) * VS_PAD + nf * 8 + r4];
                mma_tf32(oacc[nf], a0, a1, a2, a3, b0, b1);
            }
        }
    }

    // epilogue with reference's no-transpose reshape:
    // (b,h,l,kk) -> row h*128 + l/16, col (l%16)*64 + kk
    const float inv0 = 1.f / l0;
    const float inv8 = 1.f / l8;
    const int lg0 = qbase + wrow + r4;
    const int lg8 = lg0 + 8;
    #pragma unroll
    for (int nf = 0; nf < 8; nf++) {
        int d = nf * 8 + 2 * q4;
        int row0 = hh * 128 + (lg0 >> 4), col0 = (lg0 & 15) * 64 + d;
        int row8 = hh * 128 + (lg8 >> 4), col8 = (lg8 & 15) * 64 + d;
        *(float2*)(o_out + ((size_t)(b * SEQL + row0)) * DMODEL + col0) =
            make_float2(oacc[nf][0] * inv0, oacc[nf][1] * inv0);
        *(float2*)(o_out + ((size_t)(b * SEQL + row8)) * DMODEL + col8) =
            make_float2(oacc[nf][2] * inv8, oacc[nf][3] * inv8);
    }
}

// ---------------- residual add + LayerNorm ----------------------------------
__global__ __launch_bounds__(256) void add_ln_kernel(
    const float* __restrict__ a, const float* __restrict__ b,
    const float* __restrict__ g, const float* __restrict__ beta,
    float* __restrict__ out)
{
    const int row = blockIdx.x;
    const int tid = threadIdx.x;
    const float* ar = a + (size_t)row * DMODEL;
    const float* br = b + (size_t)row * DMODEL;

    float x[4];
    float sum = 0.f, sq = 0.f;
    #pragma unroll
    for (int i = 0; i < 4; i++) {
        int c = tid + i * 256;
        x[i] = ar[c] + br[c];
        sum += x[i];
        sq  += x[i] * x[i];
    }
    #pragma unroll
    for (int off = 16; off; off >>= 1) {
        sum += __shfl_xor_sync(0xffffffffu, sum, off);
        sq  += __shfl_xor_sync(0xffffffffu, sq, off);
    }
    __shared__ float ssum[8], ssq[8];
    const int wid = tid >> 5;
    if ((tid & 31) == 0) { ssum[wid] = sum; ssq[wid] = sq; }
    __syncthreads();
    sum = 0.f; sq = 0.f;
    #pragma unroll
    for (int w = 0; w < 8; w++) { sum += ssum[w]; sq += ssq[w]; }

    const float mean = sum * (1.f / DMODEL);
    const float var  = sq * (1.f / DMODEL) - mean * mean;
    const float rstd = rsqrtf(var + 1e-5f);

    float* orow = out + (size_t)row * DMODEL;
    #pragma unroll
    for (int i = 0; i < 4; i++) {
        int c = tid + i * 256;
        orow[c] = (x[i] - mean) * rstd * g[c] + beta[c];
    }
}

// ---------------- launch ----------------------------------------------------
extern "C" void kernel_launch(void* const* d_in, const int* in_sizes, int n_in,
                              void* d_out, int out_size)
{
    const float* x    = (const float*)d_in[0];
    const float* Wq   = (const float*)d_in[1];
    const float* bq   = (const float*)d_in[2];
    const float* Wk   = (const float*)d_in[3];
    const float* bk   = (const float*)d_in[4];
    const float* Wv   = (const float*)d_in[5];
    const float* bv   = (const float*)d_in[6];
    const float* Wo   = (const float*)d_in[7];
    const float* bo   = (const float*)d_in[8];
    const float* W1   = (const float*)d_in[9];
    const float* b1   = (const float*)d_in[10];
    const float* W2   = (const float*)d_in[11];
    const float* b2   = (const float*)d_in[12];
    const float* g1   = (const float*)d_in[13];
    const float* bt1  = (const float*)d_in[14];
    const float* g2   = (const float*)d_in[15];
    const float* bt2  = (const float*)d_in[16];
    float* out = (float*)d_out;

    float *q, *k, *v, *attnv, *tmp, *x1, *ff, *tmp2;
    cudaGetSymbolAddress((void**)&q,     g_q);
    cudaGetSymbolAddress((void**)&k,     g_k);
    cudaGetSymbolAddress((void**)&v,     g_v);
    cudaGetSymbolAddress((void**)&attnv, g_attnv);
    cudaGetSymbolAddress((void**)&tmp,   g_tmp);
    cudaGetSymbolAddress((void**)&x1,    g_x1);
    cudaGetSymbolAddress((void**)&ff,    g_ff);
    cudaGetSymbolAddress((void**)&tmp2,  g_tmp2);

    cudaFuncSetAttribute(attn_tc, cudaFuncAttributeMaxDynamicSharedMemorySize,
                         ATT_SMEM_BYTES);

    dim3 gD(DMODEL / 128, TOKENS / 128);   // (8, 32)
    dim3 gF(DFF / 128, TOKENS / 128);      // (32, 32)

    // QKV projections (tf32 tensor cores)
    tgemm_bias<<<gD, 256>>>(x, Wq, bq, q, TOKENS, DMODEL, DMODEL, 0);
    tgemm_bias<<<gD, 256>>>(x, Wk, bk, k, TOKENS, DMODEL, DMODEL, 0);
    tgemm_bias<<<gD, 256>>>(x, Wv, bv, v, TOKENS, DMODEL, DMODEL, 0);

    // tensor-core flash attention (reference's no-transpose reshape epilogue)
    dim3 gA(SEQL / 128, BATCH * NHEADS);   // (16, 32)
    attn_tc<<<gA, 256, ATT_SMEM_BYTES>>>(q, k, v, attnv);

    // output projection + residual LN
    tgemm_bias<<<gD, 256>>>(attnv, Wo, bo, tmp, TOKENS, DMODEL, DMODEL, 0);
    add_ln_kernel<<<TOKENS, 256>>>(tmp, x, g1, bt1, x1);

    // FFN
    tgemm_bias<<<gF, 256>>>(x1, W1, b1, ff, TOKENS, DFF, DMODEL, 1);
    tgemm_bias<<<gD, 256>>>(ff, W2, b2, tmp2, TOKENS, DMODEL, DFF, 0);
    add_ln_kernel<<<TOKENS, 256>>>(tmp2, x1, g2, bt2, out);
}

// round 4
// speedup vs baseline: 3.7943x; 1.0788x over previous
#include <cuda_runtime.h>
#include <math.h>
#include <stdint.h>

#define BATCH 2
#define SEQL  2048
#define DMODEL 1024
#define NHEADS 16
#define DK    64
#define DFF   4096
#define TOKENS (BATCH*SEQL)   // 4096

// ---------------- scratch (device globals: allocation-guard safe) -----------
__device__ float g_qkv[TOKENS*3*DMODEL];
__device__ float g_attnv[TOKENS*DMODEL];
__device__ float g_tmp[TOKENS*DMODEL];
__device__ float g_x1[TOKENS*DMODEL];
__device__ float g_ff[TOKENS*DFF];
__device__ float g_tmp2[TOKENS*DMODEL];
__device__ float g_bias3[3*DMODEL];

// ---------------- helpers ----------------------------------------------------
__device__ __forceinline__ void mma_tf32(float c[4],
    uint32_t a0, uint32_t a1, uint32_t a2, uint32_t a3,
    uint32_t b0, uint32_t b1)
{
    asm volatile(
        "mma.sync.aligned.m16n8k8.row.col.f32.tf32.tf32.f32 "
        "{%0,%1,%2,%3}, {%4,%5,%6,%7}, {%8,%9}, {%0,%1,%2,%3};"
        : "+f"(c[0]), "+f"(c[1]), "+f"(c[2]), "+f"(c[3])
        : "r"(a0), "r"(a1), "r"(a2), "r"(a3), "r"(b0), "r"(b1));
}

__device__ __forceinline__ void cp16(uint32_t dst, const void* src) {
    asm volatile("cp.async.cg.shared.global [%0], [%1], 16;" :: "r"(dst), "l"(src));
}
__device__ __forceinline__ void cp_commit() { asm volatile("cp.async.commit_group;"); }
__device__ __forceinline__ void cp_wait0()  { asm volatile("cp.async.wait_group 0;"); }

// ---------------- TF32 GEMM, 256x128 tile, BK=32, cp.async double buffer ----
// 256 thr (8 warps), warp tile 64x64 (4x8 m16n8k8 tiles). Raw fp32 bits fed to
// tf32 MMA (HW truncation). Supports fused-QKV via 3 B pointers (col select).
#define A_PAD 36
#define B_PAD 136
#define ASTG (256*A_PAD)
#define BSTG (32*B_PAD)
#define GEMM_SMEM_BYTES (2*(ASTG+BSTG)*4)

__global__ __launch_bounds__(256, 1) void tgemm_bias(
    const float* __restrict__ A,
    const float* __restrict__ B0, const float* __restrict__ B1,
    const float* __restrict__ B2,
    const float* __restrict__ bias, float* __restrict__ C,
    int M, int N, int K, int ldb, int gelu)
{
    extern __shared__ uint32_t sg[];
    uint32_t* As = sg;            // [2][256][A_PAD]
    uint32_t* Bs = sg + 2*ASTG;   // [2][32][B_PAD]
    const uint32_t asB = (uint32_t)__cvta_generic_to_shared(As);
    const uint32_t bsB = (uint32_t)__cvta_generic_to_shared(Bs);

    const int tid  = threadIdx.x;
    const int lane = tid & 31;
    const int warp = tid >> 5;
    const int r4 = lane >> 2, q4 = lane & 3;
    const int wm = (warp & 3) * 64;
    const int wn = (warp >> 2) * 64;
    const int rowBase = blockIdx.y * 256;
    const int colBase = blockIdx.x * 128;

    // fused-QKV column select (each 128-col block lies in one source matrix)
    const float* Bw = B0;
    int cb = colBase;
    if (B1 && colBase >= ldb) { Bw = B1; cb = colBase - ldb; }
    if (B2 && colBase >= 2 * ldb) { Bw = B2; cb = colBase - 2 * ldb; }

    float acc[4][8][4];
    #pragma unroll
    for (int i = 0; i < 4; i++)
        #pragma unroll
        for (int j = 0; j < 8; j++)
            #pragma unroll
            for (int r = 0; r < 4; r++) acc[i][j][r] = 0.f;

    const int NC = K / 32;

    // issue stage 0
    {
        #pragma unroll
        for (int i = 0; i < 8; i++) {
            int f = tid + i * 256;
            int r = f >> 3, c4 = (f & 7) * 4;
            cp16(asB + ((r * A_PAD + c4) << 2),
                 A + (size_t)(rowBase + r) * K + c4);
        }
        #pragma unroll
        for (int i = 0; i < 4; i++) {
            int f = tid + i * 256;
            int r = f >> 5, c4 = (f & 31) * 4;
            cp16(bsB + ((r * B_PAD + c4) << 2),
                 Bw + (size_t)r * ldb + cb + c4);
        }
        cp_commit();
    }

    for (int ic = 0; ic < NC; ic++) {
        cp_wait0();
        __syncthreads();

        if (ic + 1 < NC) {
            int st = (ic + 1) & 1;
            int k0 = (ic + 1) * 32;
            #pragma unroll
            for (int i = 0; i < 8; i++) {
                int f = tid + i * 256;
                int r = f >> 3, c4 = (f & 7) * 4;
                cp16(asB + ((st * ASTG + r * A_PAD + c4) << 2),
                     A + (size_t)(rowBase + r) * K + k0 + c4);
            }
            #pragma unroll
            for (int i = 0; i < 4; i++) {
                int f = tid + i * 256;
                int r = f >> 5, c4 = (f & 31) * 4;
                cp16(bsB + ((st * BSTG + r * B_PAD + c4) << 2),
                     Bw + (size_t)(k0 + r) * ldb + cb + c4);
            }
            cp_commit();
        }

        const uint32_t* Asl = As + (ic & 1) * ASTG;
        const uint32_t* Bsl = Bs + (ic & 1) * BSTG;
        #pragma unroll
        for (int kk = 0; kk < 4; kk++) {
            uint32_t af[4][4], bf[8][2];
            #pragma unroll
            for (int mf = 0; mf < 4; mf++) {
                int r = wm + mf * 16 + r4;
                int c = kk * 8 + q4;
                af[mf][0] = Asl[r * A_PAD + c];
                af[mf][1] = Asl[(r + 8) * A_PAD + c];
                af[mf][2] = Asl[r * A_PAD + c + 4];
                af[mf][3] = Asl[(r + 8) * A_PAD + c + 4];
            }
            #pragma unroll
            for (int nf = 0; nf < 8; nf++) {
                int cc = wn + nf * 8 + r4;
                int rr = kk * 8 + q4;
                bf[nf][0] = Bsl[rr * B_PAD + cc];
                bf[nf][1] = Bsl[(rr + 4) * B_PAD + cc];
            }
            #pragma unroll
            for (int mf = 0; mf < 4; mf++)
                #pragma unroll
                for (int nf = 0; nf < 8; nf++)
                    mma_tf32(acc[mf][nf], af[mf][0], af[mf][1], af[mf][2], af[mf][3],
                             bf[nf][0], bf[nf][1]);
        }
    }

    #pragma unroll
    for (int mf = 0; mf < 4; mf++) {
        #pragma unroll
        for (int nf = 0; nf < 8; nf++) {
            int row = rowBase + wm + mf * 16 + r4;
            int col = colBase + wn + nf * 8 + 2 * q4;
            float v0 = acc[mf][nf][0] + bias[col];
            float v1 = acc[mf][nf][1] + bias[col + 1];
            float v2 = acc[mf][nf][2] + bias[col];
            float v3 = acc[mf][nf][3] + bias[col + 1];
            if (gelu) {
                v0 = 0.5f * v0 * (1.f + erff(v0 * 0.70710678118654752f));
                v1 = 0.5f * v1 * (1.f + erff(v1 * 0.70710678118654752f));
                v2 = 0.5f * v2 * (1.f + erff(v2 * 0.70710678118654752f));
                v3 = 0.5f * v3 * (1.f + erff(v3 * 0.70710678118654752f));
            }
            *(float2*)(C + (size_t)row * N + col)       = make_float2(v0, v1);
            *(float2*)(C + (size_t)(row + 8) * N + col) = make_float2(v2, v3);
        }
    }
}

// ---------------- tensor-core flash attention, cp.async double-buffered -----
#define KS_PAD 68
#define VS_PAD 72
#define PS_PAD 132
#define KSTG (128*KS_PAD)
#define VSTG (128*VS_PAD)
#define ATT_SMEM_BYTES ((2*KSTG + 2*VSTG + 128*PS_PAD) * 4)
#define LDQKV (3*DMODEL)

__global__ __launch_bounds__(256, 1) void attn_tc(
    const float* __restrict__ qkv, float* __restrict__ o_out)
{
    extern __shared__ uint32_t sm[];
    uint32_t* Ks = sm;                      // [2][128][KS_PAD]
    uint32_t* Vs = sm + 2 * KSTG;           // [2][128][VS_PAD]
    uint32_t* Ps = sm + 2 * (KSTG + VSTG);  // [128][PS_PAD]
    const uint32_t ksB = (uint32_t)__cvta_generic_to_shared(Ks);
    const uint32_t vsB = (uint32_t)__cvta_generic_to_shared(Vs);

    const int tid  = threadIdx.x;
    const int lane = tid & 31;
    const int warp = tid >> 5;
    const int r4 = lane >> 2, q4 = lane & 3;
    const int bh = blockIdx.y;
    const int b  = bh >> 4;
    const int hh = bh & 15;
    const int qbase = blockIdx.x * 128;
    const int wrow  = warp * 16;

    const float* qp = qkv + ((size_t)(b * SEQL + qbase + wrow)) * LDQKV + hh * DK;
    const float* kbase = qkv + (size_t)b * SEQL * LDQKV + DMODEL + hh * DK;
    const float* vbase = qkv + (size_t)b * SEQL * LDQKV + 2 * DMODEL + hh * DK;

    // Q fragments: raw fp32 bits (HW tf32 truncation); scale applied to S later
    uint32_t qf[8][4];
    #pragma unroll
    for (int kk = 0; kk < 8; kk++) {
        qf[kk][0] = __float_as_uint(qp[(size_t)r4       * LDQKV + kk * 8 + q4    ]);
        qf[kk][1] = __float_as_uint(qp[(size_t)(r4 + 8) * LDQKV + kk * 8 + q4    ]);
        qf[kk][2] = __float_as_uint(qp[(size_t)r4       * LDQKV + kk * 8 + q4 + 4]);
        qf[kk][3] = __float_as_uint(qp[(size_t)(r4 + 8) * LDQKV + kk * 8 + q4 + 4]);
    }

    float oacc[8][4];
    #pragma unroll
    for (int nf = 0; nf < 8; nf++)
        #pragma unroll
        for (int r = 0; r < 4; r++) oacc[nf][r] = 0.f;

    float m0 = -1e30f, m8 = -1e30f, l0 = 0.f, l8 = 0.f;

    // issue tile 0
    {
        #pragma unroll
        for (int i = 0; i < 8; i++) {
            int f = tid + i * 256;
            int key = f >> 4, d4 = (f & 15) * 4;
            cp16(ksB + ((key * KS_PAD + d4) << 2), kbase + (size_t)key * LDQKV + d4);
            cp16(vsB + ((key * VS_PAD + d4) << 2), vbase + (size_t)key * LDQKV + d4);
        }
        cp_commit();
    }

    const int NT = SEQL / 128;
    for (int t = 0; t < NT; t++) {
        cp_wait0();
        __syncthreads();

        if (t + 1 < NT) {
            int st = (t + 1) & 1;
            int kt = (t + 1) * 128;
            #pragma unroll
            for (int i = 0; i < 8; i++) {
                int f = tid + i * 256;
                int key = f >> 4, d4 = (f & 15) * 4;
                cp16(ksB + ((st * KSTG + key * KS_PAD + d4) << 2),
                     kbase + (size_t)(kt + key) * LDQKV + d4);
                cp16(vsB + ((st * VSTG + key * VS_PAD + d4) << 2),
                     vbase + (size_t)(kt + key) * LDQKV + d4);
            }
            cp_commit();
        }

        const uint32_t* Ksl = Ks + (t & 1) * KSTG;
        const uint32_t* Vsl = Vs + (t & 1) * VSTG;

        // S = Q @ K^T (16 x 128 per warp)
        float sacc[16][4];
        #pragma unroll
        for (int nf = 0; nf < 16; nf++)
            #pragma unroll
            for (int r = 0; r < 4; r++) sacc[nf][r] = 0.f;

        #pragma unroll
        for (int kk = 0; kk < 8; kk++) {
            #pragma unroll
            for (int nf = 0; nf < 16; nf++) {
                uint32_t b0 = Ksl[(nf * 8 + r4) * KS_PAD + kk * 8 + q4];
                uint32_t b1 = Ksl[(nf * 8 + r4) * KS_PAD + kk * 8 + q4 + 4];
                mma_tf32(sacc[nf], qf[kk][0], qf[kk][1], qf[kk][2], qf[kk][3], b0, b1);
            }
        }
        #pragma unroll
        for (int nf = 0; nf < 16; nf++) {
            sacc[nf][0] *= 0.125f; sacc[nf][1] *= 0.125f;
            sacc[nf][2] *= 0.125f; sacc[nf][3] *= 0.125f;
        }

        // online softmax
        float mx0 = -1e30f, mx8 = -1e30f;
        #pragma unroll
        for (int nf = 0; nf < 16; nf++) {
            mx0 = fmaxf(mx0, fmaxf(sacc[nf][0], sacc[nf][1]));
            mx8 = fmaxf(mx8, fmaxf(sacc[nf][2], sacc[nf][3]));
        }
        mx0 = fmaxf(mx0, __shfl_xor_sync(0xffffffffu, mx0, 1));
        mx0 = fmaxf(mx0, __shfl_xor_sync(0xffffffffu, mx0, 2));
        mx8 = fmaxf(mx8, __shfl_xor_sync(0xffffffffu, mx8, 1));
        mx8 = fmaxf(mx8, __shfl_xor_sync(0xffffffffu, mx8, 2));

        float mn0 = fmaxf(m0, mx0), mn8 = fmaxf(m8, mx8);
        float sc0 = __expf(m0 - mn0), sc8 = __expf(m8 - mn8);
        m0 = mn0; m8 = mn8;
        l0 *= sc0; l8 *= sc8;
        #pragma unroll
        for (int nf = 0; nf < 8; nf++) {
            oacc[nf][0] *= sc0; oacc[nf][1] *= sc0;
            oacc[nf][2] *= sc8; oacc[nf][3] *= sc8;
        }

        float rs0 = 0.f, rs8 = 0.f;
        uint32_t* pw0 = Ps + (wrow + r4) * PS_PAD;
        uint32_t* pw8 = Ps + (wrow + r4 + 8) * PS_PAD;
        #pragma unroll
        for (int nf = 0; nf < 16; nf++) {
            float p0 = __expf(sacc[nf][0] - m0);
            float p1 = __expf(sacc[nf][1] - m0);
            float p2 = __expf(sacc[nf][2] - m8);
            float p3 = __expf(sacc[nf][3] - m8);
            rs0 += p0 + p1; rs8 += p2 + p3;
            int col = nf * 8 + 2 * q4;
            pw0[col] = __float_as_uint(p0); pw0[col + 1] = __float_as_uint(p1);
            pw8[col] = __float_as_uint(p2); pw8[col + 1] = __float_as_uint(p3);
        }
        rs0 += __shfl_xor_sync(0xffffffffu, rs0, 1);
        rs0 += __shfl_xor_sync(0xffffffffu, rs0, 2);
        rs8 += __shfl_xor_sync(0xffffffffu, rs8, 1);
        rs8 += __shfl_xor_sync(0xffffffffu, rs8, 2);
        l0 += rs0; l8 += rs8;
        __syncwarp();   // P rows are warp-private

        // O += P @ V
        #pragma unroll
        for (int kk = 0; kk < 16; kk++) {
            uint32_t a0 = Ps[(wrow + r4)     * PS_PAD + kk * 8 + q4];
            uint32_t a1 = Ps[(wrow + r4 + 8) * PS_PAD + kk * 8 + q4];
            uint32_t a2 = Ps[(wrow + r4)     * PS_PAD + kk * 8 + q4 + 4];
            uint32_t a3 = Ps[(wrow + r4 + 8) * PS_PAD + kk * 8 + q4 + 4];
            #pragma unroll
            for (int nf = 0; nf < 8; nf++) {
                uint32_t b0 = Vsl[(kk * 8 + q4)     * VS_PAD + nf * 8 + r4];
                uint32_t b1 = Vsl[(kk * 8 + q4 + 4) * VS_PAD + nf * 8 + r4];
                mma_tf32(oacc[nf], a0, a1, a2, a3, b0, b1);
            }
        }
    }

    // epilogue, reference's no-transpose reshape
    const float inv0 = 1.f / l0, inv8 = 1.f / l8;
    const int lg0 = qbase + wrow + r4;
    const int lg8 = lg0 + 8;
    #pragma unroll
    for (int nf = 0; nf < 8; nf++) {
        int d = nf * 8 + 2 * q4;
        int row0 = hh * 128 + (lg0 >> 4), col0 = (lg0 & 15) * 64 + d;
        int row8 = hh * 128 + (lg8 >> 4), col8 = (lg8 & 15) * 64 + d;
        *(float2*)(o_out + ((size_t)(b * SEQL + row0)) * DMODEL + col0) =
            make_float2(oacc[nf][0] * inv0, oacc[nf][1] * inv0);
        *(float2*)(o_out + ((size_t)(b * SEQL + row8)) * DMODEL + col8) =
            make_float2(oacc[nf][2] * inv8, oacc[nf][3] * inv8);
    }
}

// ---------------- residual add + LayerNorm ----------------------------------
__global__ __launch_bounds__(256) void add_ln_kernel(
    const float* __restrict__ a, const float* __restrict__ b,
    const float* __restrict__ g, const float* __restrict__ beta,
    float* __restrict__ out)
{
    const int row = blockIdx.x;
    const int tid = threadIdx.x;
    const float* ar = a + (size_t)row * DMODEL;
    const float* br = b + (size_t)row * DMODEL;

    float x[4];
    float sum = 0.f, sq = 0.f;
    #pragma unroll
    for (int i = 0; i < 4; i++) {
        int c = tid + i * 256;
        x[i] = ar[c] + br[c];
        sum += x[i];
        sq  += x[i] * x[i];
    }
    #pragma unroll
    for (int off = 16; off; off >>= 1) {
        sum += __shfl_xor_sync(0xffffffffu, sum, off);
        sq  += __shfl_xor_sync(0xffffffffu, sq, off);
    }
    __shared__ float ssum[8], ssq[8];
    const int wid = tid >> 5;
    if ((tid & 31) == 0) { ssum[wid] = sum; ssq[wid] = sq; }
    __syncthreads();
    sum = 0.f; sq = 0.f;
    #pragma unroll
    for (int w = 0; w < 8; w++) { sum += ssum[w]; sq += ssq[w]; }

    const float mean = sum * (1.f / DMODEL);
    const float var  = sq * (1.f / DMODEL) - mean * mean;
    const float rstd = rsqrtf(var + 1e-5f);

    float* orow = out + (size_t)row * DMODEL;
    #pragma unroll
    for (int i = 0; i < 4; i++) {
        int c = tid + i * 256;
        orow[c] = (x[i] - mean) * rstd * g[c] + beta[c];
    }
}

// ---------------- bias concat ------------------------------------------------
__global__ void concat_bias(const float* a, const float* b, const float* c,
                            float* o)
{
    int i = blockIdx.x * 256 + threadIdx.x;
    if (i < DMODEL) {
        o[i] = a[i];
        o[i + DMODEL] = b[i];
        o[i + 2 * DMODEL] = c[i];
    }
}

// ---------------- launch ----------------------------------------------------
extern "C" void kernel_launch(void* const* d_in, const int* in_sizes, int n_in,
                              void* d_out, int out_size)
{
    const float* x    = (const float*)d_in[0];
    const float* Wq   = (const float*)d_in[1];
    const float* bq   = (const float*)d_in[2];
    const float* Wk   = (const float*)d_in[3];
    const float* bk   = (const float*)d_in[4];
    const float* Wv   = (const float*)d_in[5];
    const float* bv   = (const float*)d_in[6];
    const float* Wo   = (const float*)d_in[7];
    const float* bo   = (const float*)d_in[8];
    const float* W1   = (const float*)d_in[9];
    const float* b1   = (const float*)d_in[10];
    const float* W2   = (const float*)d_in[11];
    const float* b2   = (const float*)d_in[12];
    const float* g1   = (const float*)d_in[13];
    const float* bt1  = (const float*)d_in[14];
    const float* g2   = (const float*)d_in[15];
    const float* bt2  = (const float*)d_in[16];
    float* out = (float*)d_out;

    float *qkv, *attnv, *tmp, *x1, *ff, *tmp2, *bias3;
    cudaGetSymbolAddress((void**)&qkv,   g_qkv);
    cudaGetSymbolAddress((void**)&attnv, g_attnv);
    cudaGetSymbolAddress((void**)&tmp,   g_tmp);
    cudaGetSymbolAddress((void**)&x1,    g_x1);
    cudaGetSymbolAddress((void**)&ff,    g_ff);
    cudaGetSymbolAddress((void**)&tmp2,  g_tmp2);
    cudaGetSymbolAddress((void**)&bias3, g_bias3);

    cudaFuncSetAttribute(tgemm_bias, cudaFuncAttributeMaxDynamicSharedMemorySize,
                         GEMM_SMEM_BYTES);
    cudaFuncSetAttribute(attn_tc, cudaFuncAttributeMaxDynamicSharedMemorySize,
                         ATT_SMEM_BYTES);

    concat_bias<<<4, 256>>>(bq, bk, bv, bias3);

    // fused QKV projection: [4096 x 1024] @ [1024 x 3072]
    dim3 gQKV(3 * DMODEL / 128, TOKENS / 256);  // (24, 16)
    tgemm_bias<<<gQKV, 256, GEMM_SMEM_BYTES>>>(
        x, Wq, Wk, Wv, bias3, qkv, TOKENS, 3 * DMODEL, DMODEL, DMODEL, 0);

    // tensor-core flash attention over the fused buffer
    dim3 gA(SEQL / 128, BATCH * NHEADS);        // (16, 32)
    attn_tc<<<gA, 256, ATT_SMEM_BYTES>>>(qkv, attnv);

    // output projection + residual LN
    dim3 gD(DMODEL / 128, TOKENS / 256);        // (8, 16)
    tgemm_bias<<<gD, 256, GEMM_SMEM_BYTES>>>(
        attnv, Wo, nullptr, nullptr, bo, tmp, TOKENS, DMODEL, DMODEL, DMODEL, 0);
    add_ln_kernel<<<TOKENS, 256>>>(tmp, x, g1, bt1, x1);

    // FFN
    dim3 gF(DFF / 128, TOKENS / 256);           // (32, 16)
    tgemm_bias<<<gF, 256, GEMM_SMEM_BYTES>>>(
        x1, W1, nullptr, nullptr, b1, ff, TOKENS, DFF, DMODEL, DFF, 1);
    tgemm_bias<<<gD, 256, GEMM_SMEM_BYTES>>>(
        ff, W2, nullptr, nullptr, b2, tmp2, TOKENS, DMODEL, DFF, DMODEL, 0);
    add_ln_kernel<<<TOKENS, 256>>>(tmp2, x1, g2, bt2, out);
}